// round 1
// baseline (speedup 1.0000x reference)
#include <cuda_runtime.h>
#include <cuda_bf16.h>
#include <math.h>

// SimRel: out[b][c] = dot(X[b], A[c]) / max(||X[b]|| * ||A[c]||, 1e-8)
//         with out[b][c] = 1.0 where A[c] contains any inf.
// B=262144, D=256, C=64.
//
// Strategy: 1 row per thread. Centroids live TRANSPOSED in 64KB shared
// ([k][c] layout) so one broadcast LDS.128 at (k, c4) feeds 4 classes.
// Accumulators are packed f32x2 (classes 2cp,2cp+1) driven by fma.rn.f32x2
// with a lane-duplicated x[k] -> half the FMA instruction count vs scalar
// FFMA (B300 fp32 peak is only reachable through the f32x2 pipe).

#define EPSV 1e-8f

__device__ __forceinline__ unsigned long long dup_f32x2(float v) {
    unsigned long long r;
    asm("mov.b64 %0, {%1, %1};" : "=l"(r) : "f"(v));
    return r;
}
__device__ __forceinline__ unsigned long long pack_f32x2(float lo, float hi) {
    unsigned long long r;
    asm("mov.b64 %0, {%1, %2};" : "=l"(r) : "f"(lo), "f"(hi));
    return r;
}
__device__ __forceinline__ void unpack_f32x2(unsigned long long v, float& lo, float& hi) {
    asm("mov.b64 {%0, %1}, %2;" : "=f"(lo), "=f"(hi) : "l"(v));
}
#define FMA2(acc, a, b) \
    asm("fma.rn.f32x2 %0, %1, %2, %0;" : "+l"(acc) : "l"(a), "l"(b))

__global__ void __launch_bounds__(256, 2)
SimRel_48335561949951_kernel(const float* __restrict__ X,
                             const float* __restrict__ A,
                             float* __restrict__ out,
                             int B) {
    extern __shared__ float smem[];
    float* st   = smem;                 // [256][64] transposed centroids (64KB)
    float* cn   = smem + 64 * 256;      // [64] centroid norms
    int*   infm = (int*)(cn + 64);      // [64] inf flags

    const int tid = threadIdx.x;

    // ---- Fill transposed centroid tile (coalesced global reads;
    //      one-time 32-way STS bank conflict is negligible) ----
    #pragma unroll
    for (int i = tid; i < 64 * 256; i += 256) {
        int c = i >> 8;        // 0..63
        int k = i & 255;       // 0..255
        st[k * 64 + c] = A[i]; // A is [c][k] row-major
    }
    __syncthreads();

    // ---- Per-class norm + inf flag (conflict-free: thread c reads column c) ----
    if (tid < 64) {
        int c = tid;
        float s = 0.0f;
        int f = 0;
        #pragma unroll 8
        for (int k = 0; k < 256; k++) {
            float v = st[k * 64 + c];
            s += v * v;
            f |= isinf(v);
        }
        cn[c]   = sqrtf(s);
        infm[c] = f;
    }
    __syncthreads();

    const int row = blockIdx.x * 256 + tid;
    if (row >= B) return;

    const float4* xrow = (const float4*)(X + (size_t)row * 256);

    // 32 packed accumulators: acc[cp] holds dots for classes (2cp, 2cp+1)
    unsigned long long acc[32];
    #pragma unroll
    for (int i = 0; i < 32; i++) acc[i] = 0ull;
    unsigned long long nacc = 0ull;  // packed ||x||^2 partial sums

    #pragma unroll 1
    for (int kc = 0; kc < 64; kc++) {   // 64 chunks of 4 k-values
        float4 xv = xrow[kc];

        // x-norm contribution (packed)
        unsigned long long nx01 = pack_f32x2(xv.x, xv.y);
        unsigned long long nx23 = pack_f32x2(xv.z, xv.w);
        FMA2(nacc, nx01, nx01);
        FMA2(nacc, nx23, nx23);

        unsigned long long xx0 = dup_f32x2(xv.x);
        unsigned long long xx1 = dup_f32x2(xv.y);
        unsigned long long xx2 = dup_f32x2(xv.z);
        unsigned long long xx3 = dup_f32x2(xv.w);

        const int kbase = kc * 4;
        #pragma unroll
        for (int c4 = 0; c4 < 16; c4++) {
            // k = kbase+j, classes 4*c4 .. 4*c4+3 ; broadcast LDS.128
            {
                ulonglong2 s = *(const ulonglong2*)(st + (kbase + 0) * 64 + c4 * 4);
                FMA2(acc[c4 * 2 + 0], xx0, s.x);
                FMA2(acc[c4 * 2 + 1], xx0, s.y);
            }
            {
                ulonglong2 s = *(const ulonglong2*)(st + (kbase + 1) * 64 + c4 * 4);
                FMA2(acc[c4 * 2 + 0], xx1, s.x);
                FMA2(acc[c4 * 2 + 1], xx1, s.y);
            }
            {
                ulonglong2 s = *(const ulonglong2*)(st + (kbase + 2) * 64 + c4 * 4);
                FMA2(acc[c4 * 2 + 0], xx2, s.x);
                FMA2(acc[c4 * 2 + 1], xx2, s.y);
            }
            {
                ulonglong2 s = *(const ulonglong2*)(st + (kbase + 3) * 64 + c4 * 4);
                FMA2(acc[c4 * 2 + 0], xx3, s.x);
                FMA2(acc[c4 * 2 + 1], xx3, s.y);
            }
        }
    }

    // ---- Epilogue ----
    float nlo, nhi;
    unpack_f32x2(nacc, nlo, nhi);
    float xn = sqrtf(nlo + nhi);

    float4* o4 = (float4*)(out + (size_t)row * 64);
    #pragma unroll
    for (int g = 0; g < 16; g++) {   // 4 classes per float4 store
        float d0, d1, d2, d3;
        unpack_f32x2(acc[g * 2 + 0], d0, d1);
        unpack_f32x2(acc[g * 2 + 1], d2, d3);
        int c0 = g * 4;
        float r0 = infm[c0 + 0] ? 1.0f : __fdividef(d0, fmaxf(xn * cn[c0 + 0], EPSV));
        float r1 = infm[c0 + 1] ? 1.0f : __fdividef(d1, fmaxf(xn * cn[c0 + 1], EPSV));
        float r2 = infm[c0 + 2] ? 1.0f : __fdividef(d2, fmaxf(xn * cn[c0 + 2], EPSV));
        float r3 = infm[c0 + 3] ? 1.0f : __fdividef(d3, fmaxf(xn * cn[c0 + 3], EPSV));
        float4 r; r.x = r0; r.y = r1; r.z = r2; r.w = r3;
        o4[g] = r;
    }
}

extern "C" void kernel_launch(void* const* d_in, const int* in_sizes, int n_in,
                              void* d_out, int out_size) {
    const float* X = (const float*)d_in[0];   // inputs  [B, 256] fp32
    // d_in[1] = labels (int64) — unused by the reference output
    const float* A = (const float*)d_in[2];   // class_avgs [64, 256] fp32
    float* out = (float*)d_out;

    int B = in_sizes[0] / 256;

    const int smem_bytes = (64 * 256 + 64) * (int)sizeof(float) + 64 * (int)sizeof(int);
    cudaFuncSetAttribute(SimRel_48335561949951_kernel,
                         cudaFuncAttributeMaxDynamicSharedMemorySize, smem_bytes);

    int grid = (B + 255) / 256;
    SimRel_48335561949951_kernel<<<grid, 256, smem_bytes>>>(X, A, out, B);
}

// round 2
// speedup vs baseline: 1.2587x; 1.2587x over previous
#include <cuda_runtime.h>
#include <math.h>

// SimRel: out[b][c] = dot(X[b],A[c]) / max(||X[b]||*||A[c]||, 1e-8), 1.0 if A[c] has inf.
// B=262144, D=256, C=64.
//
// R1: FMA-bound design. 2 rows/thread (centroid LDS amortized 2x), X staged
// through smem with cp.async (coalesced LDG, conflict-free pad-20 LDS),
// packed fma.rn.f32x2 accumulators (64 classes -> 32 f32x2 accs per row).

#define EPSV     1e-8f
#define THREADS  256
#define ROWS_PB  512            // 2 rows per thread
#define XPAD     20             // 16 k-floats per stage + 4 pad (conflict-free)
#define NSTAGE   16             // 256 k / 16 per stage

typedef unsigned long long ull;

__device__ __forceinline__ ull dup2(float v) {
    ull r; asm("mov.b64 %0, {%1, %1};" : "=l"(r) : "f"(v)); return r;
}
__device__ __forceinline__ ull pk2(float lo, float hi) {
    ull r; asm("mov.b64 %0, {%1, %2};" : "=l"(r) : "f"(lo), "f"(hi)); return r;
}
__device__ __forceinline__ void up2(ull v, float& lo, float& hi) {
    asm("mov.b64 {%0, %1}, %2;" : "=f"(lo), "=f"(hi) : "l"(v));
}
#define FMA2(acc, a, b) \
    asm("fma.rn.f32x2 %0, %1, %2, %0;" : "+l"(acc) : "l"(a), "l"(b))

__device__ __forceinline__ unsigned dsmem(const void* p) {
    return (unsigned)__cvta_generic_to_shared(p);
}
#define CP16(dst, src)  asm volatile("cp.async.cg.shared.global [%0], [%1], 16;" :: "r"(dst), "l"(src))
#define CP_COMMIT()     asm volatile("cp.async.commit_group;")
#define CP_WAIT0()      asm volatile("cp.async.wait_group 0;")

__global__ void __launch_bounds__(THREADS, 1)
SimRel_48335561949951_kernel(const float* __restrict__ X,
                             const float* __restrict__ A,
                             float* __restrict__ out,
                             int B) {
    extern __shared__ float smem[];
    float* ct   = smem;                       // [256][64] transposed centroids (64KB)
    float* cn   = ct + 256 * 64;              // [64] centroid norms
    int*   infm = (int*)(cn + 64);            // [64] inf flags
    float* xt   = (float*)(infm + 64);        // [2][512][XPAD] x staging (80KB)

    const int tid = threadIdx.x;
    const long long rowBase = (long long)blockIdx.x * ROWS_PB;

    // ---- issue stage 0 X load (coalesced cp.async) ----
    {
        const float* base = X + rowBase * 256;          // stage 0: k in [0,16)
        #pragma unroll
        for (int i = 0; i < 8; i++) {
            int idx = tid + i * 256;                    // 0..2047
            int r = idx >> 2, f4 = idx & 3;
            CP16(dsmem(xt + r * XPAD + f4 * 4), base + (long long)r * 256 + f4 * 4);
        }
        CP_COMMIT();
    }

    // ---- transposed centroid tile fill ----
    #pragma unroll
    for (int i = tid; i < 64 * 256; i += THREADS) {
        int c = i >> 8, k = i & 255;
        ct[k * 64 + c] = A[i];                          // A is [c][k]
    }
    __syncthreads();

    // ---- per-class norm + inf flag (conflict-free column reads) ----
    if (tid < 64) {
        int c = tid; float s = 0.0f; int f = 0;
        #pragma unroll 8
        for (int k = 0; k < 256; k++) {
            float v = ct[k * 64 + c];
            s += v * v;
            f |= isinf(v);
        }
        cn[c] = sqrtf(s);
        infm[c] = f;
    }

    // ---- accumulators: 2 rows x 64 classes, packed f32x2 ----
    ull acc0[32], acc1[32];
    #pragma unroll
    for (int i = 0; i < 32; i++) { acc0[i] = 0ull; acc1[i] = 0ull; }
    ull nacc0 = 0ull, nacc1 = 0ull;

    #pragma unroll 1
    for (int s = 0; s < NSTAGE; s++) {
        CP_WAIT0();
        __syncthreads();   // stage s data visible to all; stage s-1 compute done by all

        // prefetch stage s+1 into the other buffer (safe: last read at stage s-1)
        if (s < NSTAGE - 1) {
            const float* base = X + rowBase * 256 + (s + 1) * 16;
            float* xb = xt + ((s + 1) & 1) * (ROWS_PB * XPAD);
            #pragma unroll
            for (int i = 0; i < 8; i++) {
                int idx = tid + i * 256;
                int r = idx >> 2, f4 = idx & 3;
                CP16(dsmem(xb + r * XPAD + f4 * 4), base + (long long)r * 256 + f4 * 4);
            }
            CP_COMMIT();
        }

        const float* xb  = xt + (s & 1) * (ROWS_PB * XPAD);
        const float* x0p = xb + tid * XPAD;
        const float* x1p = xb + (tid + THREADS) * XPAD;

        #pragma unroll
        for (int kl = 0; kl < 4; kl++) {
            float4 xa = *(const float4*)(x0p + kl * 4);
            float4 xv = *(const float4*)(x1p + kl * 4);

            // ||x||^2 partials (packed)
            ull p;
            p = pk2(xa.x, xa.y); FMA2(nacc0, p, p);
            p = pk2(xa.z, xa.w); FMA2(nacc0, p, p);
            p = pk2(xv.x, xv.y); FMA2(nacc1, p, p);
            p = pk2(xv.z, xv.w); FMA2(nacc1, p, p);

            ull a0 = dup2(xa.x), a1 = dup2(xa.y), a2 = dup2(xa.z), a3 = dup2(xa.w);
            ull b0 = dup2(xv.x), b1 = dup2(xv.y), b2 = dup2(xv.z), b3 = dup2(xv.w);

            const float* cb = ct + (s * 16 + kl * 4) * 64;
            #pragma unroll
            for (int c4 = 0; c4 < 16; c4++) {
                ulonglong2 s0 = *(const ulonglong2*)(cb + 0 * 64 + c4 * 4);
                ulonglong2 s1 = *(const ulonglong2*)(cb + 1 * 64 + c4 * 4);
                ulonglong2 s2 = *(const ulonglong2*)(cb + 2 * 64 + c4 * 4);
                ulonglong2 s3 = *(const ulonglong2*)(cb + 3 * 64 + c4 * 4);
                FMA2(acc0[c4*2+0], a0, s0.x); FMA2(acc0[c4*2+1], a0, s0.y);
                FMA2(acc1[c4*2+0], b0, s0.x); FMA2(acc1[c4*2+1], b0, s0.y);
                FMA2(acc0[c4*2+0], a1, s1.x); FMA2(acc0[c4*2+1], a1, s1.y);
                FMA2(acc1[c4*2+0], b1, s1.x); FMA2(acc1[c4*2+1], b1, s1.y);
                FMA2(acc0[c4*2+0], a2, s2.x); FMA2(acc0[c4*2+1], a2, s2.y);
                FMA2(acc1[c4*2+0], b2, s2.x); FMA2(acc1[c4*2+1], b2, s2.y);
                FMA2(acc0[c4*2+0], a3, s3.x); FMA2(acc0[c4*2+1], a3, s3.y);
                FMA2(acc1[c4*2+0], b3, s3.x); FMA2(acc1[c4*2+1], b3, s3.y);
            }
        }
    }

    // ---- epilogue: both rows ----
    float nlo, nhi;
    up2(nacc0, nlo, nhi); float xn0 = sqrtf(nlo + nhi);
    up2(nacc1, nlo, nhi); float xn1 = sqrtf(nlo + nhi);

    long long r0g = rowBase + tid;
    long long r1g = rowBase + THREADS + tid;

    float4* o0 = (float4*)(out + r0g * 64);
    float4* o1 = (float4*)(out + r1g * 64);
    #pragma unroll
    for (int g = 0; g < 16; g++) {
        int c0 = g * 4;
        float w0 = cn[c0 + 0], w1 = cn[c0 + 1], w2 = cn[c0 + 2], w3 = cn[c0 + 3];
        int   f0 = infm[c0+0], f1 = infm[c0+1], f2 = infm[c0+2], f3 = infm[c0+3];

        float d0, d1, d2, d3;
        up2(acc0[g*2+0], d0, d1); up2(acc0[g*2+1], d2, d3);
        float4 r;
        r.x = f0 ? 1.0f : __fdividef(d0, fmaxf(xn0 * w0, EPSV));
        r.y = f1 ? 1.0f : __fdividef(d1, fmaxf(xn0 * w1, EPSV));
        r.z = f2 ? 1.0f : __fdividef(d2, fmaxf(xn0 * w2, EPSV));
        r.w = f3 ? 1.0f : __fdividef(d3, fmaxf(xn0 * w3, EPSV));
        if (r0g < B) o0[g] = r;

        up2(acc1[g*2+0], d0, d1); up2(acc1[g*2+1], d2, d3);
        r.x = f0 ? 1.0f : __fdividef(d0, fmaxf(xn1 * w0, EPSV));
        r.y = f1 ? 1.0f : __fdividef(d1, fmaxf(xn1 * w1, EPSV));
        r.z = f2 ? 1.0f : __fdividef(d2, fmaxf(xn1 * w2, EPSV));
        r.w = f3 ? 1.0f : __fdividef(d3, fmaxf(xn1 * w3, EPSV));
        if (r1g < B) o1[g] = r;
    }
}

extern "C" void kernel_launch(void* const* d_in, const int* in_sizes, int n_in,
                              void* d_out, int out_size) {
    const float* X = (const float*)d_in[0];   // inputs [B, 256] fp32
    // d_in[1] = labels (unused)
    const float* A = (const float*)d_in[2];   // class_avgs [64, 256] fp32
    float* out = (float*)d_out;

    int B = in_sizes[0] / 256;

    const int smem_bytes = (64 * 256 + 64) * 4 + 64 * 4 + 2 * ROWS_PB * XPAD * 4;
    cudaFuncSetAttribute(SimRel_48335561949951_kernel,
                         cudaFuncAttributeMaxDynamicSharedMemorySize, smem_bytes);

    int grid = (B + ROWS_PB - 1) / ROWS_PB;
    SimRel_48335561949951_kernel<<<grid, THREADS, smem_bytes>>>(X, A, out, B);
}

// round 4
// speedup vs baseline: 1.5856x; 1.2598x over previous
#include <cuda_runtime.h>
#include <cstdint>
#include <math.h>

// SimRel via bf16-split mma.sync (HMMA) GEMM — tcgen05 unavailable (harness
// ptxas targets plain sm_103, not sm_103a; mma.sync/ldmatrix are sm_80+).
// out[b][c] = dot(X[b],A[c]) * rsqrt(|X[b]|^2) * rsqrt(|A[c]|^2); 1.0 if A[c] has inf.
// D = Xhi*Ahi + Xhi*Alo + Xlo*Ahi, fp32 accumulate (3 HMMA passes).
// B=262144, D=256, C=64.

#define THREADS 256
#define SPITCH  264                 // bf16 elems per smem row (256 + 8 pad) = 528 B
#define SROW    528                 // bytes

// ---- smem layout (bytes) ----
#define S_AHI   0                   // [64 x 264] bf16    33792
#define S_ALO   33792               //                    33792
#define S_XHI   67584               // [128 x 264] bf16   67584
#define S_XLO   135168              //                    67584
#define S_XINV  202752              // [128] f32            512
#define S_CNI   203264              // [64] f32             256
#define S_INF   203520              // [64] int             256
#define S_TOTAL 203776

__device__ __forceinline__ void sts64(uint32_t a, uint32_t x, uint32_t y) {
    asm volatile("st.shared.v2.b32 [%0], {%1,%2};" :: "r"(a), "r"(x), "r"(y));
}
__device__ __forceinline__ void ldsm4(uint32_t a, uint32_t& r0, uint32_t& r1,
                                      uint32_t& r2, uint32_t& r3) {
    asm volatile("ldmatrix.sync.aligned.m8n8.x4.shared.b16 {%0,%1,%2,%3}, [%4];"
                 : "=r"(r0), "=r"(r1), "=r"(r2), "=r"(r3) : "r"(a));
}
__device__ __forceinline__ void mma16816(float* c, uint32_t a0, uint32_t a1,
                                         uint32_t a2, uint32_t a3,
                                         uint32_t b0, uint32_t b1) {
    asm volatile("mma.sync.aligned.m16n8k16.row.col.f32.bf16.bf16.f32 "
                 "{%0,%1,%2,%3}, {%4,%5,%6,%7}, {%8,%9}, {%0,%1,%2,%3};"
                 : "+f"(c[0]), "+f"(c[1]), "+f"(c[2]), "+f"(c[3])
                 : "r"(a0), "r"(a1), "r"(a2), "r"(a3), "r"(b0), "r"(b1));
}

// fp32 float4 -> hi (truncated bf16x2 pair) + lo (rn bf16x2 of residual)
__device__ __forceinline__ void cvt_split(float4 v, uint32_t& h0, uint32_t& h1,
                                          uint32_t& l0, uint32_t& l1) {
    uint32_t xb = __float_as_uint(v.x), yb = __float_as_uint(v.y);
    uint32_t zb = __float_as_uint(v.z), wb = __float_as_uint(v.w);
    h0 = __byte_perm(xb, yb, 0x7632);
    h1 = __byte_perm(zb, wb, 0x7632);
    float lx = v.x - __uint_as_float(xb & 0xFFFF0000u);
    float ly = v.y - __uint_as_float(yb & 0xFFFF0000u);
    float lz = v.z - __uint_as_float(zb & 0xFFFF0000u);
    float lw = v.w - __uint_as_float(wb & 0xFFFF0000u);
    asm("cvt.rn.bf16x2.f32 %0, %1, %2;" : "=r"(l0) : "f"(ly), "f"(lx));
    asm("cvt.rn.bf16x2.f32 %0, %1, %2;" : "=r"(l1) : "f"(lw), "f"(lz));
}

__device__ __forceinline__ float sum8(float4 a, float4 b) {
    float s = a.x * a.x;
    s = fmaf(a.y, a.y, s); s = fmaf(a.z, a.z, s); s = fmaf(a.w, a.w, s);
    s = fmaf(b.x, b.x, s); s = fmaf(b.y, b.y, s);
    s = fmaf(b.z, b.z, s); s = fmaf(b.w, b.w, s);
    return s;
}

__global__ void __launch_bounds__(THREADS, 1)
SimRel_48335561949951_kernel(const float* __restrict__ X,
                             const float* __restrict__ A,
                             float* __restrict__ out,
                             int B, int ntiles) {
    extern __shared__ char smem[];
    const uint32_t sb = (uint32_t)__cvta_generic_to_shared(smem);
    float* xinv_s = (float*)(smem + S_XINV);
    float* cni_s  = (float*)(smem + S_CNI);
    int*   inf_s  = (int*)(smem + S_INF);

    const int tid = threadIdx.x, w = tid >> 5, l = tid & 31;

    // ---- centroid conversion + norms (8 rows per warp, once) ----
    #pragma unroll
    for (int rr = 0; rr < 8; rr++) {
        int r = w * 8 + rr;
        const float4* p = (const float4*)(A + (size_t)r * 256);
        float4 v0 = p[l], v1 = p[32 + l];
        uint32_t h0, h1, q0, q1;
        cvt_split(v0, h0, h1, q0, q1);
        sts64(sb + S_AHI + r * SROW + 8 * l, h0, h1);
        sts64(sb + S_ALO + r * SROW + 8 * l, q0, q1);
        cvt_split(v1, h0, h1, q0, q1);
        sts64(sb + S_AHI + r * SROW + 256 + 8 * l, h0, h1);
        sts64(sb + S_ALO + r * SROW + 256 + 8 * l, q0, q1);
        float ss = sum8(v0, v1);
        int bad = (fabsf(v0.x) == INFINITY) | (fabsf(v0.y) == INFINITY) |
                  (fabsf(v0.z) == INFINITY) | (fabsf(v0.w) == INFINITY) |
                  (fabsf(v1.x) == INFINITY) | (fabsf(v1.y) == INFINITY) |
                  (fabsf(v1.z) == INFINITY) | (fabsf(v1.w) == INFINITY);
        #pragma unroll
        for (int o = 16; o; o >>= 1) ss += __shfl_xor_sync(0xffffffffu, ss, o);
        unsigned m = __ballot_sync(0xffffffffu, bad);
        if (l == 0) { cni_s[r] = rsqrtf(ss); inf_s[r] = (m != 0); }
    }
    __syncthreads();

    // ---- per-lane ldmatrix address components ----
    const int t8 = l >> 3;
    const uint32_t frag_off = (uint32_t)(((t8 & 1) * 8 + (l & 7)) * SROW + (t8 >> 1) * 16);
    const uint32_t xfh = sb + S_XHI + (uint32_t)(w * 16) * SROW + frag_off;
    const uint32_t xfl = sb + S_XLO + (uint32_t)(w * 16) * SROW + frag_off;
    const uint32_t afh = sb + S_AHI + frag_off;
    const uint32_t afl = sb + S_ALO + frag_off;

    const uint32_t xsh = sb + S_XHI + (uint32_t)(w * 16) * SROW;
    const uint32_t xsl = sb + S_XLO + (uint32_t)(w * 16) * SROW;

    const int qr = l >> 2, qc = (l & 3) * 2;

    // ---- persistent tile loop: each warp owns 16 rows, no inter-warp sync ----
    for (int tile = blockIdx.x; tile < ntiles; tile += gridDim.x) {
        const long long tb = (long long)tile * 128;

        // phase 1: load + split-convert 16 rows (4-row chunks for MLP)
        const float4* p = (const float4*)(X + (tb + w * 16) * 256);
        #pragma unroll
        for (int rc = 0; rc < 16; rc += 4) {
            float4 v0[4], v1[4];
            #pragma unroll
            for (int j = 0; j < 4; j++) {
                v0[j] = p[(rc + j) * 64 + l];
                v1[j] = p[(rc + j) * 64 + 32 + l];
            }
            #pragma unroll
            for (int j = 0; j < 4; j++) {
                int rr = rc + j;
                uint32_t h0, h1, q0, q1;
                cvt_split(v0[j], h0, h1, q0, q1);
                sts64(xsh + rr * SROW + 8 * l, h0, h1);
                sts64(xsl + rr * SROW + 8 * l, q0, q1);
                cvt_split(v1[j], h0, h1, q0, q1);
                sts64(xsh + rr * SROW + 256 + 8 * l, h0, h1);
                sts64(xsl + rr * SROW + 256 + 8 * l, q0, q1);
                float ss = sum8(v0[j], v1[j]);
                #pragma unroll
                for (int o = 16; o; o >>= 1) ss += __shfl_xor_sync(0xffffffffu, ss, o);
                if (l == 0) xinv_s[w * 16 + rr] = rsqrtf(ss);
            }
        }
        __syncwarp();

        // phase 2: 3 bf16-split passes x 16 k-steps of m16n8k16
        float acc[8][4];
        #pragma unroll
        for (int nb = 0; nb < 8; nb++)
            #pragma unroll
            for (int j = 0; j < 4; j++) acc[nb][j] = 0.0f;

        #pragma unroll
        for (int pass = 0; pass < 3; pass++) {
            const uint32_t xf = (pass == 2) ? xfl : xfh;
            const uint32_t af = (pass == 1) ? afl : afh;
            #pragma unroll
            for (int s = 0; s < 16; s++) {
                uint32_t a0, a1, a2, a3;
                ldsm4(xf + s * 32, a0, a1, a2, a3);
                #pragma unroll
                for (int h = 0; h < 4; h++) {
                    uint32_t b0, b1, b2, b3;
                    ldsm4(af + h * (16 * SROW) + s * 32, b0, b1, b2, b3);
                    mma16816(acc[h * 2 + 0], a0, a1, a2, a3, b0, b2);
                    mma16816(acc[h * 2 + 1], a0, a1, a2, a3, b1, b3);
                }
            }
        }

        // phase 3: epilogue — scale + store (warp-owned rows, STG.64)
        float xi0 = xinv_s[w * 16 + qr];
        float xi1 = xinv_s[w * 16 + 8 + qr];
        long long r0g = tb + w * 16 + qr;
        float* o0 = out + r0g * 64;
        float* o1 = o0 + 8 * 64;
        #pragma unroll
        for (int nb = 0; nb < 8; nb++) {
            int c0 = nb * 8 + qc;
            float2 cn2 = *(const float2*)(cni_s + c0);
            int2   ff  = *(const int2*)(inf_s + c0);
            float2 s0, s1;
            s0.x = ff.x ? 1.0f : acc[nb][0] * xi0 * cn2.x;
            s0.y = ff.y ? 1.0f : acc[nb][1] * xi0 * cn2.y;
            s1.x = ff.x ? 1.0f : acc[nb][2] * xi1 * cn2.x;
            s1.y = ff.y ? 1.0f : acc[nb][3] * xi1 * cn2.y;
            *(float2*)(o0 + c0) = s0;
            *(float2*)(o1 + c0) = s1;
        }
        __syncwarp();   // protect X smem (WAR) + xinv before next tile's writes
    }
}

extern "C" void kernel_launch(void* const* d_in, const int* in_sizes, int n_in,
                              void* d_out, int out_size) {
    const float* X = (const float*)d_in[0];   // inputs [B, 256] fp32
    // d_in[1] = labels (unused)
    const float* A = (const float*)d_in[2];   // class_avgs [64, 256] fp32
    float* out = (float*)d_out;

    int B = in_sizes[0] / 256;
    int ntiles = (B + 127) / 128;

    int dev = 0, nsm = 148;
    cudaGetDevice(&dev);
    cudaDeviceGetAttribute(&nsm, cudaDevAttrMultiProcessorCount, dev);
    if (nsm > ntiles) nsm = ntiles;

    cudaFuncSetAttribute(SimRel_48335561949951_kernel,
                         cudaFuncAttributeMaxDynamicSharedMemorySize, S_TOTAL);

    SimRel_48335561949951_kernel<<<nsm, THREADS, S_TOTAL>>>(X, A, out, B, ntiles);
}